// round 2
// baseline (speedup 1.0000x reference)
#include <cuda_runtime.h>
#include <math.h>

// Problem constants
#define N_   128
#define T_   1024
#define C_   256
#define L_   128
#define S_   257          // 2L+1 extended states
#define TPB  288          // 9 warps: 257 states, 256 loaders, warp 8 = Z-reducer
#define PFD  8            // prefetch ring depth
#define NEGE (-(1 << 28)) // "-inf" exponent

__device__ float g_loss[N_];   // per-sample loss / tl

// ---------------------------------------------------------------------------
// Fused kernel: one block per sample n.
//  thread tid < 257 : DP state s = tid, value = mant * 2^exp (per-state exp)
//  thread tid < 256 : loader for class c = tid (8-deep register prefetch ring,
//                     publishes e^x into double-buffered rowbuf)
//  warp 8 (tid>=256): reduces each published row to Z_t, Kahan-accumulates
//                     sum_t log Z_t  (replaces the old separate K1 pass)
// ---------------------------------------------------------------------------
__global__ void __launch_bounds__(TPB) ctc_fused(const float* __restrict__ preds,
                                                 const int*   __restrict__ targets) {
    const int n   = blockIdx.x;
    const int tid = threadIdx.x;

    __shared__ __align__(16) float  rowbuf[2][C_];   // e^x rows (double buffer)
    __shared__ float2 albuf[2][S_ + 2];              // [0],[1] = -inf padding
    __shared__ int    stg[L_];
    __shared__ float  s_slz;

    const float* P = preds + (size_t)n * T_ * C_;
    const float LOG2E = 1.4426950408889634f;

    if (tid < L_) stg[tid] = targets[n * L_ + tid];
    if (tid < 2) {
        albuf[0][tid] = make_float2(0.0f, __int_as_float(NEGE));
        albuf[1][tid] = make_float2(0.0f, __int_as_float(NEGE));
    }
    __syncthreads();

    // per-state class + skip permission
    const int  s      = tid;
    const bool active = (s < S_);
    int  cls  = 0;
    bool skip = false;
    if (active && (s & 1)) {
        cls  = stg[(s - 1) >> 1];
        skip = (s < 3) || (cls != stg[(s - 3) >> 1]);
    }

    // ---- prologue: publish e^x for rows 0,1; stage row 2; fill ring 3..10
    const int c = tid;
    float r2 = 0.0f;
    float pf[PFD];
    if (c < C_) {
        rowbuf[0][c] = exp2f(P[0 * C_ + c] * LOG2E);
        rowbuf[1][c] = exp2f(P[1 * C_ + c] * LOG2E);
        r2           = exp2f(P[2 * C_ + c] * LOG2E);
        #pragma unroll
        for (int i = 0; i < PFD; i++) pf[i] = P[(size_t)(3 + i) * C_ + c];
    }
    __syncthreads();

    // alpha init at t=0 (unnormalized emissions; logZ handled globally)
    float am = 0.0f; int ae = NEGE; float ecur = 0.0f;
    if (active) {
        if (s == 0)      { am = rowbuf[0][0];   ae = 0; }
        else if (s == 1) { am = rowbuf[0][cls]; ae = 0; }
        ecur = rowbuf[1][cls];                         // emission for t=1
        albuf[0][2 + s] = make_float2(am, __int_as_float(ae));
    }

    // warp 8: Z for rows 0 and 1 (Kahan accumulate sum of log Z)
    float zacc = 0.0f, zcomp = 0.0f;
    if (tid >= 256) {
        const int l = tid - 256;
        #pragma unroll
        for (int r = 0; r < 2; r++) {
            const float4* rb = reinterpret_cast<const float4*>(rowbuf[r]);
            float4 aa = rb[l], bb = rb[l + 32];
            float sv = aa.x + aa.y + aa.z + aa.w + bb.x + bb.y + bb.z + bb.w;
            #pragma unroll
            for (int o = 16; o; o >>= 1) sv += __shfl_xor_sync(0xffffffffu, sv, o);
            float lg = logf(sv);
            float y = lg - zcomp, t2 = zacc + y;
            zcomp = (t2 - zacc) - y; zacc = t2;
        }
    }
    __syncthreads();
    if (c < C_) rowbuf[0][c] = r2;     // row 2 -> slot 0
    __syncthreads();

    // One DP time step. SLOT = static prefetch-ring index.
    #define DP_STEP(TI, SLOT)                                                  \
    {                                                                          \
        const int t  = (TI);                                                   \
        const int pr = (t - 1) & 1, cu = t & 1;                                \
        float anew = 0.0f; int enew = NEGE; float enext = 0.0f;                \
        if (active) {                                                          \
            float2 v1 = albuf[pr][1 + s];      /* state s-1 */                 \
            float2 v2 = albuf[pr][s];          /* state s-2 */                 \
            int e1 = __float_as_int(v1.y);                                     \
            int e2 = skip ? __float_as_int(v2.y) : NEGE;                       \
            int E  = max(ae, max(e1, e2));                                     \
            float f0 = __int_as_float((127 + max(ae - E, -127)) << 23);        \
            float f1 = __int_as_float((127 + max(e1 - E, -127)) << 23);        \
            float f2 = __int_as_float((127 + max(e2 - E, -127)) << 23);        \
            float sum = fmaf(v1.x, f1, am * f0);                               \
            sum = fmaf(v2.x, f2, sum);                                         \
            float val = sum * ecur;                                            \
            int bits = __float_as_int(val);                                    \
            anew = __int_as_float((bits & 0x807FFFFF) | 0x3F800000);           \
            if (bits == 0) anew = 0.0f;                                        \
            enew = E + ((bits >> 23) & 255) - 127;                             \
            enext = rowbuf[(t + 1) & 1][cls];                                  \
            albuf[cu][2 + s] = make_float2(anew, __int_as_float(enew));        \
        }                                                                      \
        if (c < C_) {                                                          \
            if (t + 2 < T_) rowbuf[cu][c] = exp2f(pf[SLOT] * LOG2E);           \
            const int ld = t + 2 + PFD;                                        \
            if (ld < T_) pf[SLOT] = P[(size_t)ld * C_ + c];                    \
        }                                                                      \
        if (tid >= 256 && t + 1 < T_) {     /* Z for row t+1 (stable slot) */  \
            const float4* rb = reinterpret_cast<const float4*>(rowbuf[(t + 1) & 1]); \
            const int l = tid - 256;                                           \
            float4 aa = rb[l], bb = rb[l + 32];                                \
            float sv = aa.x + aa.y + aa.z + aa.w + bb.x + bb.y + bb.z + bb.w;  \
            _Pragma("unroll")                                                  \
            for (int o = 16; o; o >>= 1) sv += __shfl_xor_sync(0xffffffffu, sv, o); \
            float lg = logf(sv);                                               \
            float y = lg - zcomp, t2 = zacc + y;                               \
            zcomp = (t2 - zacc) - y; zacc = t2;                                \
        }                                                                      \
        __syncthreads();                                                       \
        am = anew; ae = enew; ecur = enext;                                    \
    }

    // t = 1 .. 1016 in chunks of 8 (static ring slots)
    for (int tb = 1; tb + 8 <= T_; tb += 8) {
        DP_STEP(tb + 0, 0) DP_STEP(tb + 1, 1) DP_STEP(tb + 2, 2) DP_STEP(tb + 3, 3)
        DP_STEP(tb + 4, 4) DP_STEP(tb + 5, 5) DP_STEP(tb + 6, 6) DP_STEP(tb + 7, 7)
    }
    // tail: t = 1017 .. 1023
    {
        const int tb = 1017;
        DP_STEP(tb + 0, 0) DP_STEP(tb + 1, 1) DP_STEP(tb + 2, 2) DP_STEP(tb + 3, 3)
        DP_STEP(tb + 4, 4) DP_STEP(tb + 5, 5) DP_STEP(tb + 6, 6)
    }
    #undef DP_STEP

    if (tid == 256) s_slz = zacc;      // all lanes equal after butterfly
    __syncthreads();

    // epilogue
    if (tid == 0) {
        int tl = 0;
        for (int i = 0; i < L_; i++) tl += (stg[i] != 0);
        float2 va = albuf[(T_ - 1) & 1][2 + 2 * tl];
        float2 vb = albuf[(T_ - 1) & 1][2 + 2 * tl - 1];
        int ea = __float_as_int(va.y), eb = __float_as_int(vb.y);
        int E  = max(ea, eb);
        float fa = __int_as_float((127 + max(ea - E, -127)) << 23);
        float fb = __int_as_float((127 + max(eb - E, -127)) << 23);
        float v  = va.x * fa + vb.x * fb;
        float loss = 0.0f;
        if (v > 0.0f && E > NEGE / 2) {
            float fin = logf(v) + (float)E * 0.69314718055994531f - s_slz;
            if (fin >= -1e29f) loss = -fin;
        }
        g_loss[n] = loss / (float)(tl > 0 ? tl : 1);
    }
}

// ---------------------------------------------------------------------------
// batch mean -> d_out[0]
// ---------------------------------------------------------------------------
__global__ void k_reduce(float* __restrict__ out) {
    const int tid  = threadIdx.x;
    const int wid  = tid >> 5;
    const int lane = tid & 31;
    __shared__ float sh[4];

    float v = (tid < N_) ? g_loss[tid] : 0.0f;
    #pragma unroll
    for (int o = 16; o; o >>= 1) v += __shfl_xor_sync(0xffffffffu, v, o);
    if (lane == 0) sh[wid] = v;
    __syncthreads();
    if (tid == 0) out[0] = (sh[0] + sh[1] + sh[2] + sh[3]) / (float)N_;
}

// ---------------------------------------------------------------------------
extern "C" void kernel_launch(void* const* d_in, const int* in_sizes, int n_in,
                              void* d_out, int out_size) {
    const float* preds   = (const float*)d_in[0];
    const int*   targets = (const int*)d_in[1];

    ctc_fused<<<N_, TPB>>>(preds, targets);
    k_reduce<<<1, 128>>>((float*)d_out);
}

// round 3
// speedup vs baseline: 2.2499x; 2.2499x over previous
#include <cuda_runtime.h>
#include <math.h>

// Problem constants
#define N_   128
#define T_   1024
#define C_   256
#define L_   128
#define S_   257          // 2L+1 extended states
#define TPB  288          // 9 warps: states 0..256, loaders 0..255
#define PFD  8            // prefetch ring depth
#define NEGE (-(1 << 28)) // "-inf" exponent

__device__ float g_slz[N_];    // sum_t logZ[n,t]
__device__ float g_loss[N_];   // per-sample loss / tl

// ---------------------------------------------------------------------------
// K1: per-sample sum over t of log-sum-exp normalizer.  Pure bandwidth
// (134 MB streamed once).  One block per n; each warp owns rows t = wid mod 32.
// ---------------------------------------------------------------------------
__global__ void __launch_bounds__(1024) k1_rownorm(const float* __restrict__ preds) {
    const int n    = blockIdx.x;
    const int wid  = threadIdx.x >> 5;
    const int lane = threadIdx.x & 31;
    const float LOG2E = 1.4426950408889634f;

    float acc = 0.0f;
    for (int t = wid; t < T_; t += 32) {
        const float4* row = reinterpret_cast<const float4*>(preds + ((size_t)n * T_ + t) * C_);
        float4 v0 = row[lane];
        float4 v1 = row[lane + 32];
        float s = exp2f(v0.x * LOG2E) + exp2f(v0.y * LOG2E)
                + exp2f(v0.z * LOG2E) + exp2f(v0.w * LOG2E)
                + exp2f(v1.x * LOG2E) + exp2f(v1.y * LOG2E)
                + exp2f(v1.z * LOG2E) + exp2f(v1.w * LOG2E);
        #pragma unroll
        for (int o = 16; o; o >>= 1) s += __shfl_xor_sync(0xffffffffu, s, o);
        if (lane == 0) acc += logf(s);
    }

    __shared__ float part[32];
    if (lane == 0) part[wid] = acc;
    __syncthreads();
    if (threadIdx.x == 0) {
        float tot = 0.0f;
        #pragma unroll
        for (int w = 0; w < 32; w++) tot += part[w];
        g_slz[n] = tot;
    }
}

// ---------------------------------------------------------------------------
// K2: CTC forward DP, scaled linear domain with per-state (mantissa, exp).
// One block per n; thread s < 257 owns extended state s; threads < 256 also
// stream logit rows (8-deep register prefetch ring) and publish e^x into a
// double-buffered smem row cache.  Exponent re-extraction every 8 steps only;
// in between, mantissas drift (exact algebra, fp32 range is ample).
// ---------------------------------------------------------------------------
__global__ void __launch_bounds__(TPB) k2_dp(const float* __restrict__ preds,
                                             const int*   __restrict__ targets) {
    const int n   = blockIdx.x;
    const int tid = threadIdx.x;

    __shared__ __align__(16) float rowbuf[2][C_];   // e^x rows (double buffer)
    __shared__ float2 albuf[2][S_ + 2];             // [0],[1] = -inf padding
    __shared__ int    stg[L_];

    const float* P = preds + (size_t)n * T_ * C_;
    const float LOG2E = 1.4426950408889634f;

    if (tid < L_) stg[tid] = targets[n * L_ + tid];
    if (tid < 2) {
        albuf[0][tid] = make_float2(0.0f, __int_as_float(NEGE));
        albuf[1][tid] = make_float2(0.0f, __int_as_float(NEGE));
    }
    __syncthreads();

    const int  s      = tid;
    const bool active = (s < S_);
    int  cls  = 0;
    bool skip = false;
    if (active && (s & 1)) {
        cls  = stg[(s - 1) >> 1];
        skip = (s < 3) || (cls != stg[(s - 3) >> 1]);
    }

    // prologue: publish e^x rows 0,1; stage row 2; fill prefetch ring (rows 3..10)
    const int c = tid;
    float r2 = 0.0f;
    float pf[PFD];
    if (c < C_) {
        rowbuf[0][c] = exp2f(P[0 * C_ + c] * LOG2E);
        rowbuf[1][c] = exp2f(P[1 * C_ + c] * LOG2E);
        r2           = exp2f(P[2 * C_ + c] * LOG2E);
        #pragma unroll
        for (int i = 0; i < PFD; i++) pf[i] = P[(size_t)(3 + i) * C_ + c];
    }
    __syncthreads();

    float am = 0.0f; int ae = NEGE; float ecur = 0.0f;
    if (active) {
        if (s == 0)      { am = rowbuf[0][0];   ae = 0; }
        else if (s == 1) { am = rowbuf[0][cls]; ae = 0; }
        ecur = rowbuf[1][cls];
        albuf[0][2 + s] = make_float2(am, __int_as_float(ae));
    }
    __syncthreads();
    if (c < C_) rowbuf[0][c] = r2;     // row 2 -> slot 0
    __syncthreads();

    // One DP time step.  SLOT = static prefetch-ring index; renorm on SLOT==7.
    #define DP_STEP(TI, SLOT)                                                  \
    {                                                                          \
        const int t  = (TI);                                                   \
        const int pr = (t - 1) & 1, cu = t & 1;                                \
        float anew = 0.0f; int enew = NEGE; float enext = 0.0f;                \
        if (active) {                                                          \
            float2 v1 = albuf[pr][1 + s];      /* state s-1 */                 \
            float2 v2 = albuf[pr][s];          /* state s-2 */                 \
            int e1 = __float_as_int(v1.y);                                     \
            int e2 = skip ? __float_as_int(v2.y) : NEGE;                       \
            int E  = max(ae, max(e1, e2));                                     \
            float f0 = __int_as_float((127 + max(ae - E, -127)) << 23);        \
            float f1 = __int_as_float((127 + max(e1 - E, -127)) << 23);        \
            float f2 = __int_as_float((127 + max(e2 - E, -127)) << 23);        \
            float sum = fmaf(v1.x, f1, am * f0);                               \
            sum = fmaf(v2.x, f2, sum);                                         \
            float val = sum * ecur;                                            \
            if ((SLOT) == 7) {            /* periodic exponent extraction */   \
                int bits = __float_as_int(val);                                \
                anew = __int_as_float((bits & 0x807FFFFF) | 0x3F800000);       \
                enew = E + ((bits >> 23) & 255) - 127;                         \
                if (bits == 0) { anew = 0.0f; enew = NEGE; }                   \
            } else {                                                           \
                anew = val;                                                    \
                enew = (val == 0.0f) ? NEGE : E;                               \
            }                                                                  \
            enext = rowbuf[(t + 1) & 1][cls];                                  \
            albuf[cu][2 + s] = make_float2(anew, __int_as_float(enew));        \
        }                                                                      \
        if (c < C_) {                                                          \
            if (t + 2 < T_) rowbuf[cu][c] = exp2f(pf[SLOT] * LOG2E);           \
            const int ld = t + 2 + PFD;                                        \
            if (ld < T_) pf[SLOT] = P[(size_t)ld * C_ + c];                    \
        }                                                                      \
        __syncthreads();                                                       \
        am = anew; ae = enew; ecur = enext;                                    \
    }

    // t = 1 .. 1016 in chunks of 8 (static ring slots)
    for (int tb = 1; tb + 8 <= T_; tb += 8) {
        DP_STEP(tb + 0, 0) DP_STEP(tb + 1, 1) DP_STEP(tb + 2, 2) DP_STEP(tb + 3, 3)
        DP_STEP(tb + 4, 4) DP_STEP(tb + 5, 5) DP_STEP(tb + 6, 6) DP_STEP(tb + 7, 7)
    }
    // tail: t = 1017 .. 1023 (no renorm; epilogue handles drifted mantissas)
    {
        const int tb = 1017;
        DP_STEP(tb + 0, 0) DP_STEP(tb + 1, 1) DP_STEP(tb + 2, 2) DP_STEP(tb + 3, 3)
        DP_STEP(tb + 4, 4) DP_STEP(tb + 5, 5) DP_STEP(tb + 6, 6)
    }
    #undef DP_STEP

    // epilogue
    if (tid == 0) {
        int tl = 0;
        for (int i = 0; i < L_; i++) tl += (stg[i] != 0);
        float2 va = albuf[(T_ - 1) & 1][2 + 2 * tl];
        float2 vb = albuf[(T_ - 1) & 1][2 + 2 * tl - 1];
        int ea = __float_as_int(va.y), eb = __float_as_int(vb.y);
        int E  = max(ea, eb);
        float fa = __int_as_float((127 + max(ea - E, -127)) << 23);
        float fb = __int_as_float((127 + max(eb - E, -127)) << 23);
        float v  = va.x * fa + vb.x * fb;
        float loss = 0.0f;
        if (v > 0.0f && E > NEGE / 2) {
            float fin = logf(v) + (float)E * 0.69314718055994531f - g_slz[n];
            if (fin >= -1e29f) loss = -fin;
        }
        g_loss[n] = loss / (float)(tl > 0 ? tl : 1);
    }
}

// ---------------------------------------------------------------------------
// K3: batch mean -> d_out[0]
// ---------------------------------------------------------------------------
__global__ void k_reduce(float* __restrict__ out) {
    const int tid  = threadIdx.x;
    const int wid  = tid >> 5;
    const int lane = tid & 31;
    __shared__ float sh[4];

    float v = (tid < N_) ? g_loss[tid] : 0.0f;
    #pragma unroll
    for (int o = 16; o; o >>= 1) v += __shfl_xor_sync(0xffffffffu, v, o);
    if (lane == 0) sh[wid] = v;
    __syncthreads();
    if (tid == 0) out[0] = (sh[0] + sh[1] + sh[2] + sh[3]) / (float)N_;
}

// Profiling aid: pads the launch sequence so ncu's "-s 5 -c 1" lands on k2_dp
// (sequence 0:k1 1:k2 2:red 3:nop 4:k1 5:k2).
__global__ void k_nop() {}

// ---------------------------------------------------------------------------
extern "C" void kernel_launch(void* const* d_in, const int* in_sizes, int n_in,
                              void* d_out, int out_size) {
    const float* preds   = (const float*)d_in[0];
    const int*   targets = (const int*)d_in[1];

    k1_rownorm<<<N_, 1024>>>(preds);
    k2_dp<<<N_, TPB>>>(preds, targets);
    k_reduce<<<1, 128>>>((float*)d_out);
    k_nop<<<1, 32>>>();
}